// round 1
// baseline (speedup 1.0000x reference)
#include <cuda_runtime.h>

#define NN 50000
#define EE 800000
#define FD 128
#define ZD 64

// ---------------- scratch (device globals; no allocation allowed) ----------
__device__ __align__(256) float g_bufA[NN * FD];
__device__ __align__(256) float g_bufB[NN * FD];
__device__ int   g_cnt[NN];
__device__ int   g_cursor[NN];
__device__ int   g_off[NN + 1];
__device__ int   g_bsum[64];
__device__ int   g_boff[64];
__device__ float g_dis[NN];
__device__ int   g_csr_src[EE];
__device__ float g_csr_norm[EE];
__device__ int   g_is64;

// ---------------- edge dtype detection (int32 vs int64) --------------------
// If edge_index is int64 (values < 50000), every odd 32-bit word is 0.
__global__ void k_detect(const int* __restrict__ ei32) {
    int t = threadIdx.x;              // 32 threads
    int v = ei32[2 * t + 1];
    unsigned m = __ballot_sync(0xffffffffu, v != 0);
    if (t == 0) g_is64 = (m == 0) ? 1 : 0;
}

__device__ __forceinline__ int edge_at(const void* eiv, long idx) {
    if (g_is64) return (int)((const long long*)eiv)[idx];
    return ((const int*)eiv)[idx];
}

// ---------------- preprocessing --------------------------------------------
__global__ void k_zero_cnt() {
    int i = blockIdx.x * blockDim.x + threadIdx.x;
    if (i < NN) g_cnt[i] = 0;
}

__global__ void k_count(const void* __restrict__ eiv) {
    int e = blockIdx.x * blockDim.x + threadIdx.x;
    if (e < EE) {
        int d = edge_at(eiv, (long)EE + e);
        atomicAdd(&g_cnt[d], 1);
    }
}

__global__ void k_degdis() {
    int i = blockIdx.x * blockDim.x + threadIdx.x;
    if (i < NN) g_dis[i] = rsqrtf((float)(g_cnt[i] + 1));  // +1 self loop, deg>=1
}

// exclusive scan of g_cnt into g_off (3-pass)
__global__ void k_scan1() {
    __shared__ int ws[32];
    int i = blockIdx.x * 1024 + threadIdx.x;
    int lane = threadIdx.x & 31, wid = threadIdx.x >> 5;
    int v = (i < NN) ? g_cnt[i] : 0;
    int orig = v;
#pragma unroll
    for (int d = 1; d < 32; d <<= 1) {
        int n = __shfl_up_sync(0xffffffffu, v, d);
        if (lane >= d) v += n;
    }
    if (lane == 31) ws[wid] = v;
    __syncthreads();
    if (wid == 0) {
        int s = ws[lane];
#pragma unroll
        for (int d = 1; d < 32; d <<= 1) {
            int n = __shfl_up_sync(0xffffffffu, s, d);
            if (lane >= d) s += n;
        }
        ws[lane] = s;
    }
    __syncthreads();
    int incl = v + (wid > 0 ? ws[wid - 1] : 0);
    if (i < NN) g_off[i] = incl - orig;
    if (threadIdx.x == 1023) g_bsum[blockIdx.x] = incl;
}

__global__ void k_scan2(int nblk) {
    __shared__ int w0sum;
    int t = threadIdx.x, lane = t & 31, wid = t >> 5;   // 64 threads
    int v = (t < nblk) ? g_bsum[t] : 0;
    int orig = v;
#pragma unroll
    for (int d = 1; d < 32; d <<= 1) {
        int n = __shfl_up_sync(0xffffffffu, v, d);
        if (lane >= d) v += n;
    }
    if (wid == 0 && lane == 31) w0sum = v;
    __syncthreads();
    int incl = v + (wid == 1 ? w0sum : 0);
    if (t < nblk) g_boff[t] = incl - orig;
}

__global__ void k_scan3() {
    int i = blockIdx.x * blockDim.x + threadIdx.x;
    if (i < NN) {
        g_off[i] += g_boff[i >> 10];
        g_cursor[i] = 0;
    }
    if (i == 0) g_off[NN] = EE;
}

__global__ void k_fill(const void* __restrict__ eiv) {
    int e = blockIdx.x * blockDim.x + threadIdx.x;
    if (e < EE) {
        int s = edge_at(eiv, e);
        int d = edge_at(eiv, (long)EE + e);
        int pos = g_off[d] + atomicAdd(&g_cursor[d], 1);
        g_csr_src[pos]  = s;
        g_csr_norm[pos] = g_dis[s] * g_dis[d];
    }
}

// ---------------- fp32 SIMT GEMM:  C[M x 128] = A[M x K] @ B[K x 128] ------
// SPLIT=1: B = [Wm | Ws] (each K x 64), add bias, write to two outputs.
template <int SPLIT>
__global__ __launch_bounds__(256) void k_gemm(
    const float* __restrict__ A, int K,
    const float* __restrict__ B1, const float* __restrict__ B2,
    const float* __restrict__ bias1, const float* __restrict__ bias2,
    float* __restrict__ C1, float* __restrict__ C2)
{
    __shared__ float As[16][128];
    __shared__ float Bs[16][128];
    const int tid  = threadIdx.x;
    const int tcol = tid & 15;     // 16 col tiles of 8
    const int trow = tid >> 4;     // 16 row tiles of 8
    const int rowBase = blockIdx.x * 128;
    const int aRow = tid >> 2;             // 0..63
    const int aCol = (tid & 3) << 2;       // 0,4,8,12
    const int bRow = tid >> 5;             // 0..7
    const int bCol = (tid & 31) << 2;      // 0..124

    float acc[8][8];
#pragma unroll
    for (int i = 0; i < 8; i++)
#pragma unroll
        for (int j = 0; j < 8; j++) acc[i][j] = 0.f;

    for (int k0 = 0; k0 < K; k0 += 16) {
#pragma unroll
        for (int r = 0; r < 2; r++) {
            int row = rowBase + aRow + r * 64;
            float4 v = make_float4(0.f, 0.f, 0.f, 0.f);
            if (row < NN) v = *reinterpret_cast<const float4*>(&A[(long)row * K + k0 + aCol]);
            As[aCol + 0][aRow + r * 64] = v.x;
            As[aCol + 1][aRow + r * 64] = v.y;
            As[aCol + 2][aRow + r * 64] = v.z;
            As[aCol + 3][aRow + r * 64] = v.w;
        }
#pragma unroll
        for (int r = 0; r < 2; r++) {
            int kk = k0 + bRow + r * 8;
            float4 v;
            if (SPLIT) {
                v = (bCol < 64)
                    ? *reinterpret_cast<const float4*>(&B1[(long)kk * 64 + bCol])
                    : *reinterpret_cast<const float4*>(&B2[(long)kk * 64 + bCol - 64]);
            } else {
                v = *reinterpret_cast<const float4*>(&B1[(long)kk * 128 + bCol]);
            }
            *reinterpret_cast<float4*>(&Bs[bRow + r * 8][bCol]) = v;
        }
        __syncthreads();
#pragma unroll
        for (int k = 0; k < 16; k++) {
            float4 a0 = *reinterpret_cast<const float4*>(&As[k][trow * 8]);
            float4 a1 = *reinterpret_cast<const float4*>(&As[k][trow * 8 + 4]);
            float4 b0 = *reinterpret_cast<const float4*>(&Bs[k][tcol * 8]);
            float4 b1 = *reinterpret_cast<const float4*>(&Bs[k][tcol * 8 + 4]);
            float ra[8] = {a0.x, a0.y, a0.z, a0.w, a1.x, a1.y, a1.z, a1.w};
            float rb[8] = {b0.x, b0.y, b0.z, b0.w, b1.x, b1.y, b1.z, b1.w};
#pragma unroll
            for (int i = 0; i < 8; i++)
#pragma unroll
                for (int j = 0; j < 8; j++)
                    acc[i][j] = fmaf(ra[i], rb[j], acc[i][j]);
        }
        __syncthreads();
    }

#pragma unroll
    for (int i = 0; i < 8; i++) {
        int row = rowBase + trow * 8 + i;
        if (row >= NN) continue;
#pragma unroll
        for (int j = 0; j < 8; j += 4) {
            int col = tcol * 8 + j;
            float4 v = make_float4(acc[i][j], acc[i][j + 1], acc[i][j + 2], acc[i][j + 3]);
            if (SPLIT) {
                if (col < 64) {
                    v.x += bias1[col];     v.y += bias1[col + 1];
                    v.z += bias1[col + 2]; v.w += bias1[col + 3];
                    *reinterpret_cast<float4*>(&C1[(long)row * 64 + col]) = v;
                } else {
                    int c = col - 64;
                    v.x += bias2[c];     v.y += bias2[c + 1];
                    v.z += bias2[c + 2]; v.w += bias2[c + 3];
                    *reinterpret_cast<float4*>(&C2[(long)row * 64 + c]) = v;
                }
            } else {
                *reinterpret_cast<float4*>(&C1[(long)row * 128 + col]) = v;
            }
        }
    }
}

// ---------------- aggregation:  out[i] = sum_{e:dst=i} norm_e*G[src_e] + dis_i^2*G[i]
// one warp per node; lane handles 4 features (float4); MODE=1 adds bias+relu.
template <int MODE>
__global__ __launch_bounds__(256) void k_agg(
    const float4* __restrict__ G4, const float* __restrict__ bias,
    float4* __restrict__ O4)
{
    int warp = (blockIdx.x * blockDim.x + threadIdx.x) >> 5;
    int lane = threadIdx.x & 31;
    if (warp >= NN) return;
    int e0 = g_off[warp], e1 = g_off[warp + 1];
    float dii = g_dis[warp];
    float w0 = dii * dii;
    float4 gs = G4[(long)warp * 32 + lane];
    float4 acc;
    acc.x = w0 * gs.x; acc.y = w0 * gs.y; acc.z = w0 * gs.z; acc.w = w0 * gs.w;
#pragma unroll 4
    for (int e = e0; e < e1; e++) {
        int   s = g_csr_src[e];       // warp-broadcast load
        float w = g_csr_norm[e];
        float4 m = G4[(long)s * 32 + lane];
        acc.x = fmaf(w, m.x, acc.x);
        acc.y = fmaf(w, m.y, acc.y);
        acc.z = fmaf(w, m.z, acc.z);
        acc.w = fmaf(w, m.w, acc.w);
    }
    if (MODE == 1) {
        float4 b = reinterpret_cast<const float4*>(bias)[lane];
        acc.x = fmaxf(acc.x + b.x, 0.f);
        acc.y = fmaxf(acc.y + b.y, 0.f);
        acc.z = fmaxf(acc.z + b.z, 0.f);
        acc.w = fmaxf(acc.w + b.w, 0.f);
    }
    O4[(long)warp * 32 + lane] = acc;
}

// ---------------- launch ----------------------------------------------------
extern "C" void kernel_launch(void* const* d_in, const int* in_sizes, int n_in,
                              void* d_out, int out_size) {
    const float* x  = (const float*)d_in[0];
    const void*  ei = d_in[1];
    const float* W1 = (const float*)d_in[2];
    const float* b1 = (const float*)d_in[3];
    const float* W2 = (const float*)d_in[4];
    const float* b2 = (const float*)d_in[5];
    const float* Wm = (const float*)d_in[6];
    const float* bm = (const float*)d_in[7];
    const float* Ws = (const float*)d_in[8];
    const float* bs = (const float*)d_in[9];
    float* outM = (float*)d_out;
    float* outS = outM + (long)NN * ZD;

    float *pA = nullptr, *pB = nullptr;
    cudaGetSymbolAddress((void**)&pA, g_bufA);
    cudaGetSymbolAddress((void**)&pB, g_bufB);

    const int T = 256;
    const int nblk_scan = (NN + 1023) / 1024;

    k_detect<<<1, 32>>>((const int*)ei);
    k_zero_cnt<<<(NN + T - 1) / T, T>>>();
    k_count<<<(EE + T - 1) / T, T>>>(ei);
    k_degdis<<<(NN + T - 1) / T, T>>>();
    k_scan1<<<nblk_scan, 1024>>>();
    k_scan2<<<1, 64>>>(nblk_scan);
    k_scan3<<<(NN + T - 1) / T, T>>>();
    k_fill<<<(EE + T - 1) / T, T>>>(ei);

    const int gb = (NN + 127) / 128;             // 391 blocks
    const int ab = (NN * 32 + T - 1) / T;        // 6250 blocks

    // layer 1: G = x @ W1 ; h1 = relu(A G + b1)
    k_gemm<0><<<gb, 256>>>(x, 512, W1, nullptr, nullptr, nullptr, pA, nullptr);
    k_agg<1><<<ab, T>>>((const float4*)pA, b1, (float4*)pB);
    // layer 2: G = h1 @ W2 ; h2 = relu(A G + b2)
    k_gemm<0><<<gb, 256>>>(pB, 128, W2, nullptr, nullptr, nullptr, pA, nullptr);
    k_agg<1><<<ab, T>>>((const float4*)pA, b2, (float4*)pB);
    // heads: AG = A h2 ; z_mean = AG Wm + bm ; z_log_std = AG Ws + bs
    k_agg<0><<<ab, T>>>((const float4*)pB, nullptr, (float4*)pA);
    k_gemm<1><<<gb, 256>>>(pA, 128, Wm, Ws, bm, bs, outM, outS);
}

// round 2
// speedup vs baseline: 1.0043x; 1.0043x over previous
#include <cuda_runtime.h>

#define NN 50000
#define EE 800000
#define FD 128
#define ZD 64

// ---------------- scratch (device globals; no allocation allowed) ----------
__device__ __align__(256) float g_bufA[NN * FD];
__device__ __align__(256) float g_bufB[NN * FD];
__device__ int   g_cnt[NN];
__device__ int   g_cursor[NN];
__device__ int   g_off[NN + 1];
__device__ int   g_bsum[64];
__device__ int   g_boff[64];
__device__ float g_dis[NN];
__device__ int   g_csr_src[EE];
__device__ float g_csr_norm[EE];
__device__ int   g_is64;

// ---------------- edge dtype detection (int32 vs int64) --------------------
// If edge_index is int64 (values < 50000), every odd 32-bit word is 0.
__global__ void k_detect(const int* __restrict__ ei32) {
    int t = threadIdx.x;              // 32 threads
    int v = ei32[2 * t + 1];
    unsigned m = __ballot_sync(0xffffffffu, v != 0);
    if (t == 0) g_is64 = (m == 0) ? 1 : 0;
}

__device__ __forceinline__ int edge_at(const void* eiv, long idx) {
    if (g_is64) return (int)((const long long*)eiv)[idx];
    return ((const int*)eiv)[idx];
}

// ---------------- preprocessing --------------------------------------------
__global__ void k_zero_cnt() {
    int i = blockIdx.x * blockDim.x + threadIdx.x;
    if (i < NN) g_cnt[i] = 0;
}

__global__ void k_count(const void* __restrict__ eiv) {
    int e = blockIdx.x * blockDim.x + threadIdx.x;
    if (e < EE) {
        int d = edge_at(eiv, (long)EE + e);
        atomicAdd(&g_cnt[d], 1);
    }
}

__global__ void k_degdis() {
    int i = blockIdx.x * blockDim.x + threadIdx.x;
    if (i < NN) g_dis[i] = rsqrtf((float)(g_cnt[i] + 1));  // +1 self loop, deg>=1
}

// exclusive scan of g_cnt into g_off (3-pass)
__global__ void k_scan1() {
    __shared__ int ws[32];
    int i = blockIdx.x * 1024 + threadIdx.x;
    int lane = threadIdx.x & 31, wid = threadIdx.x >> 5;
    int v = (i < NN) ? g_cnt[i] : 0;
    int orig = v;
#pragma unroll
    for (int d = 1; d < 32; d <<= 1) {
        int n = __shfl_up_sync(0xffffffffu, v, d);
        if (lane >= d) v += n;
    }
    if (lane == 31) ws[wid] = v;
    __syncthreads();
    if (wid == 0) {
        int s = ws[lane];
#pragma unroll
        for (int d = 1; d < 32; d <<= 1) {
            int n = __shfl_up_sync(0xffffffffu, s, d);
            if (lane >= d) s += n;
        }
        ws[lane] = s;
    }
    __syncthreads();
    int incl = v + (wid > 0 ? ws[wid - 1] : 0);
    if (i < NN) g_off[i] = incl - orig;
    if (threadIdx.x == 1023) g_bsum[blockIdx.x] = incl;
}

__global__ void k_scan2(int nblk) {
    __shared__ int w0sum;
    int t = threadIdx.x, lane = t & 31, wid = t >> 5;   // 64 threads
    int v = (t < nblk) ? g_bsum[t] : 0;
    int orig = v;
#pragma unroll
    for (int d = 1; d < 32; d <<= 1) {
        int n = __shfl_up_sync(0xffffffffu, v, d);
        if (lane >= d) v += n;
    }
    if (wid == 0 && lane == 31) w0sum = v;
    __syncthreads();
    int incl = v + (wid == 1 ? w0sum : 0);
    if (t < nblk) g_boff[t] = incl - orig;
}

__global__ void k_scan3() {
    int i = blockIdx.x * blockDim.x + threadIdx.x;
    if (i < NN) {
        g_off[i] += g_boff[i >> 10];
        g_cursor[i] = 0;
    }
    if (i == 0) g_off[NN] = EE;
}

__global__ void k_fill(const void* __restrict__ eiv) {
    int e = blockIdx.x * blockDim.x + threadIdx.x;
    if (e < EE) {
        int s = edge_at(eiv, e);
        int d = edge_at(eiv, (long)EE + e);
        int pos = g_off[d] + atomicAdd(&g_cursor[d], 1);
        g_csr_src[pos]  = s;
        g_csr_norm[pos] = g_dis[s] * g_dis[d];
    }
}

// ---------------- fp32 SIMT GEMM:  C[M x 128] = A[M x K] @ B[K x 128] ------
// SPLIT=1: B = [Wm | Ws] (each K x 64), add bias, write to two outputs.
template <int SPLIT>
__global__ __launch_bounds__(256) void k_gemm(
    const float* __restrict__ A, int K,
    const float* __restrict__ B1, const float* __restrict__ B2,
    const float* __restrict__ bias1, const float* __restrict__ bias2,
    float* __restrict__ C1, float* __restrict__ C2)
{
    __shared__ float As[16][128];
    __shared__ float Bs[16][128];
    const int tid  = threadIdx.x;
    const int tcol = tid & 15;     // 16 col tiles of 8
    const int trow = tid >> 4;     // 16 row tiles of 8
    const int rowBase = blockIdx.x * 128;
    const int aRow = tid >> 2;             // 0..63
    const int aCol = (tid & 3) << 2;       // 0,4,8,12
    const int bRow = tid >> 5;             // 0..7
    const int bCol = (tid & 31) << 2;      // 0..124

    float acc[8][8];
#pragma unroll
    for (int i = 0; i < 8; i++)
#pragma unroll
        for (int j = 0; j < 8; j++) acc[i][j] = 0.f;

    for (int k0 = 0; k0 < K; k0 += 16) {
#pragma unroll
        for (int r = 0; r < 2; r++) {
            int row = rowBase + aRow + r * 64;
            float4 v = make_float4(0.f, 0.f, 0.f, 0.f);
            if (row < NN) v = *reinterpret_cast<const float4*>(&A[(long)row * K + k0 + aCol]);
            As[aCol + 0][aRow + r * 64] = v.x;
            As[aCol + 1][aRow + r * 64] = v.y;
            As[aCol + 2][aRow + r * 64] = v.z;
            As[aCol + 3][aRow + r * 64] = v.w;
        }
#pragma unroll
        for (int r = 0; r < 2; r++) {
            int kk = k0 + bRow + r * 8;
            float4 v;
            if (SPLIT) {
                v = (bCol < 64)
                    ? *reinterpret_cast<const float4*>(&B1[(long)kk * 64 + bCol])
                    : *reinterpret_cast<const float4*>(&B2[(long)kk * 64 + bCol - 64]);
            } else {
                v = *reinterpret_cast<const float4*>(&B1[(long)kk * 128 + bCol]);
            }
            *reinterpret_cast<float4*>(&Bs[bRow + r * 8][bCol]) = v;
        }
        __syncthreads();
#pragma unroll
        for (int k = 0; k < 16; k++) {
            float4 a0 = *reinterpret_cast<const float4*>(&As[k][trow * 8]);
            float4 a1 = *reinterpret_cast<const float4*>(&As[k][trow * 8 + 4]);
            float4 b0 = *reinterpret_cast<const float4*>(&Bs[k][tcol * 8]);
            float4 b1 = *reinterpret_cast<const float4*>(&Bs[k][tcol * 8 + 4]);
            float ra[8] = {a0.x, a0.y, a0.z, a0.w, a1.x, a1.y, a1.z, a1.w};
            float rb[8] = {b0.x, b0.y, b0.z, b0.w, b1.x, b1.y, b1.z, b1.w};
#pragma unroll
            for (int i = 0; i < 8; i++)
#pragma unroll
                for (int j = 0; j < 8; j++)
                    acc[i][j] = fmaf(ra[i], rb[j], acc[i][j]);
        }
        __syncthreads();
    }

#pragma unroll
    for (int i = 0; i < 8; i++) {
        int row = rowBase + trow * 8 + i;
        if (row >= NN) continue;
#pragma unroll
        for (int j = 0; j < 8; j += 4) {
            int col = tcol * 8 + j;
            float4 v = make_float4(acc[i][j], acc[i][j + 1], acc[i][j + 2], acc[i][j + 3]);
            if (SPLIT) {
                if (col < 64) {
                    v.x += bias1[col];     v.y += bias1[col + 1];
                    v.z += bias1[col + 2]; v.w += bias1[col + 3];
                    *reinterpret_cast<float4*>(&C1[(long)row * 64 + col]) = v;
                } else {
                    int c = col - 64;
                    v.x += bias2[c];     v.y += bias2[c + 1];
                    v.z += bias2[c + 2]; v.w += bias2[c + 3];
                    *reinterpret_cast<float4*>(&C2[(long)row * 64 + c]) = v;
                }
            } else {
                *reinterpret_cast<float4*>(&C1[(long)row * 128 + col]) = v;
            }
        }
    }
}

// ---------------- aggregation:  out[i] = sum_{e:dst=i} norm_e*G[src_e] + dis_i^2*G[i]
// one warp per node; lane handles 4 features (float4); MODE=1 adds bias+relu.
template <int MODE>
__global__ __launch_bounds__(256) void k_agg(
    const float4* __restrict__ G4, const float* __restrict__ bias,
    float4* __restrict__ O4)
{
    int warp = (blockIdx.x * blockDim.x + threadIdx.x) >> 5;
    int lane = threadIdx.x & 31;
    if (warp >= NN) return;
    int e0 = g_off[warp], e1 = g_off[warp + 1];
    float dii = g_dis[warp];
    float w0 = dii * dii;
    float4 gs = G4[(long)warp * 32 + lane];
    float4 acc;
    acc.x = w0 * gs.x; acc.y = w0 * gs.y; acc.z = w0 * gs.z; acc.w = w0 * gs.w;
#pragma unroll 4
    for (int e = e0; e < e1; e++) {
        int   s = g_csr_src[e];       // warp-broadcast load
        float w = g_csr_norm[e];
        float4 m = G4[(long)s * 32 + lane];
        acc.x = fmaf(w, m.x, acc.x);
        acc.y = fmaf(w, m.y, acc.y);
        acc.z = fmaf(w, m.z, acc.z);
        acc.w = fmaf(w, m.w, acc.w);
    }
    if (MODE == 1) {
        float4 b = reinterpret_cast<const float4*>(bias)[lane];
        acc.x = fmaxf(acc.x + b.x, 0.f);
        acc.y = fmaxf(acc.y + b.y, 0.f);
        acc.z = fmaxf(acc.z + b.z, 0.f);
        acc.w = fmaxf(acc.w + b.w, 0.f);
    }
    O4[(long)warp * 32 + lane] = acc;
}

// ---------------- launch ----------------------------------------------------
extern "C" void kernel_launch(void* const* d_in, const int* in_sizes, int n_in,
                              void* d_out, int out_size) {
    const float* x  = (const float*)d_in[0];
    const void*  ei = d_in[1];
    const float* W1 = (const float*)d_in[2];
    const float* b1 = (const float*)d_in[3];
    const float* W2 = (const float*)d_in[4];
    const float* b2 = (const float*)d_in[5];
    const float* Wm = (const float*)d_in[6];
    const float* bm = (const float*)d_in[7];
    const float* Ws = (const float*)d_in[8];
    const float* bs = (const float*)d_in[9];
    float* outM = (float*)d_out;
    float* outS = outM + (long)NN * ZD;

    float *pA = nullptr, *pB = nullptr;
    cudaGetSymbolAddress((void**)&pA, g_bufA);
    cudaGetSymbolAddress((void**)&pB, g_bufB);

    const int T = 256;
    const int nblk_scan = (NN + 1023) / 1024;

    k_detect<<<1, 32>>>((const int*)ei);
    k_zero_cnt<<<(NN + T - 1) / T, T>>>();
    k_count<<<(EE + T - 1) / T, T>>>(ei);
    k_degdis<<<(NN + T - 1) / T, T>>>();
    k_scan1<<<nblk_scan, 1024>>>();
    k_scan2<<<1, 64>>>(nblk_scan);
    k_scan3<<<(NN + T - 1) / T, T>>>();
    k_fill<<<(EE + T - 1) / T, T>>>(ei);

    const int gb = (NN + 127) / 128;             // 391 blocks
    const int ab = (NN * 32 + T - 1) / T;        // 6250 blocks

    // layer 1: G = x @ W1 ; h1 = relu(A G + b1)
    k_gemm<0><<<gb, 256>>>(x, 512, W1, nullptr, nullptr, nullptr, pA, nullptr);
    k_agg<1><<<ab, T>>>((const float4*)pA, b1, (float4*)pB);
    // layer 2: G = h1 @ W2 ; h2 = relu(A G + b2)
    k_gemm<0><<<gb, 256>>>(pB, 128, W2, nullptr, nullptr, nullptr, pA, nullptr);
    k_agg<1><<<ab, T>>>((const float4*)pA, b2, (float4*)pB);
    // heads: AG = A h2 ; z_mean = AG Wm + bm ; z_log_std = AG Ws + bs
    k_agg<0><<<ab, T>>>((const float4*)pB, nullptr, (float4*)pA);
    k_gemm<1><<<gb, 256>>>(pA, 128, Wm, Ws, bm, bs, outM, outS);
}

// round 5
// speedup vs baseline: 1.5301x; 1.5235x over previous
#include <cuda_runtime.h>
#include <cuda_bf16.h>
#include <cstdint>

#define NN 50000
#define EE 800000
#define FD 128
#define ZD 64

// ---------------- scratch (device globals; no allocation allowed) ----------
__device__ __align__(256) float g_bufA[NN * FD];
__device__ __align__(256) float g_bufB[NN * FD];
__device__ __align__(256) __nv_bfloat16 g_Bh16[128 * 512];
__device__ __align__(256) __nv_bfloat16 g_Bl16[128 * 512];
__device__ int   g_cnt[NN];
__device__ int   g_cursor[NN];
__device__ int   g_off[NN + 1];
__device__ int   g_bsum[64];
__device__ int   g_boff[64];
__device__ float g_dis[NN];
__device__ int   g_csr_src[EE];
__device__ float g_csr_norm[EE];
__device__ int   g_is64;

// ---------------- PTX helpers ----------------------------------------------
__device__ __forceinline__ uint32_t smem_u32(const void* p) {
    uint32_t a;
    asm("{ .reg .u64 t; cvta.to.shared.u64 t, %1; cvt.u32.u64 %0, t; }"
        : "=r"(a) : "l"(p));
    return a;
}

#define LDSM_X4(r0, r1, r2, r3, addr) \
    asm volatile("ldmatrix.sync.aligned.m8n8.x4.shared.b16 {%0,%1,%2,%3}, [%4];" \
        : "=r"(r0), "=r"(r1), "=r"(r2), "=r"(r3) : "r"(addr))

#define MMA_BF16(d, a, b0, b1) \
    asm volatile("mma.sync.aligned.m16n8k16.row.col.f32.bf16.bf16.f32 " \
        "{%0,%1,%2,%3}, {%4,%5,%6,%7}, {%8,%9}, {%0,%1,%2,%3};" \
        : "+f"((d)[0]), "+f"((d)[1]), "+f"((d)[2]), "+f"((d)[3]) \
        : "r"((a)[0]), "r"((a)[1]), "r"((a)[2]), "r"((a)[3]), "r"(b0), "r"(b1))

// ---------------- edge dtype detection (int32 vs int64) --------------------
__global__ void k_detect(const int* __restrict__ ei32) {
    int t = threadIdx.x;
    int v = ei32[2 * t + 1];
    unsigned m = __ballot_sync(0xffffffffu, v != 0);
    if (t == 0) g_is64 = (m == 0) ? 1 : 0;
}

__device__ __forceinline__ int edge_at(const void* eiv, long idx) {
    if (g_is64) return (int)((const long long*)eiv)[idx];
    return ((const int*)eiv)[idx];
}

// ---------------- preprocessing --------------------------------------------
__global__ void k_zero_cnt() {
    int i = blockIdx.x * blockDim.x + threadIdx.x;
    if (i < NN) g_cnt[i] = 0;
}

__global__ void k_count(const void* __restrict__ eiv) {
    int e = blockIdx.x * blockDim.x + threadIdx.x;
    if (e < EE) {
        int d = edge_at(eiv, (long)EE + e);
        atomicAdd(&g_cnt[d], 1);
    }
}

__global__ void k_degdis() {
    int i = blockIdx.x * blockDim.x + threadIdx.x;
    if (i < NN) g_dis[i] = rsqrtf((float)(g_cnt[i] + 1));
}

__global__ void k_scan1() {
    __shared__ int ws[32];
    int i = blockIdx.x * 1024 + threadIdx.x;
    int lane = threadIdx.x & 31, wid = threadIdx.x >> 5;
    int v = (i < NN) ? g_cnt[i] : 0;
    int orig = v;
#pragma unroll
    for (int d = 1; d < 32; d <<= 1) {
        int n = __shfl_up_sync(0xffffffffu, v, d);
        if (lane >= d) v += n;
    }
    if (lane == 31) ws[wid] = v;
    __syncthreads();
    if (wid == 0) {
        int s = ws[lane];
#pragma unroll
        for (int d = 1; d < 32; d <<= 1) {
            int n = __shfl_up_sync(0xffffffffu, s, d);
            if (lane >= d) s += n;
        }
        ws[lane] = s;
    }
    __syncthreads();
    int incl = v + (wid > 0 ? ws[wid - 1] : 0);
    if (i < NN) g_off[i] = incl - orig;
    if (threadIdx.x == 1023) g_bsum[blockIdx.x] = incl;
}

__global__ void k_scan2(int nblk) {
    __shared__ int w0sum;
    int t = threadIdx.x, lane = t & 31, wid = t >> 5;
    int v = (t < nblk) ? g_bsum[t] : 0;
    int orig = v;
#pragma unroll
    for (int d = 1; d < 32; d <<= 1) {
        int n = __shfl_up_sync(0xffffffffu, v, d);
        if (lane >= d) v += n;
    }
    if (wid == 0 && lane == 31) w0sum = v;
    __syncthreads();
    int incl = v + (wid == 1 ? w0sum : 0);
    if (t < nblk) g_boff[t] = incl - orig;
}

__global__ void k_scan3() {
    int i = blockIdx.x * blockDim.x + threadIdx.x;
    if (i < NN) {
        g_off[i] += g_boff[i >> 10];
        g_cursor[i] = 0;
    }
    if (i == 0) g_off[NN] = EE;
}

__global__ void k_fill(const void* __restrict__ eiv) {
    int e = blockIdx.x * blockDim.x + threadIdx.x;
    if (e < EE) {
        int s = edge_at(eiv, e);
        int d = edge_at(eiv, (long)EE + e);
        int pos = g_off[d] + atomicAdd(&g_cursor[d], 1);
        g_csr_src[pos]  = s;
        g_csr_norm[pos] = g_dis[s] * g_dis[d];
    }
}

// ---------------- W prep: split to bf16 hi/lo, transpose to [N=128][K] -----
__global__ void k_prepB(const float* __restrict__ Wa, const float* __restrict__ Wb,
                        int K, int split) {
    int i = blockIdx.x * blockDim.x + threadIdx.x;
    if (i >= 128 * K) return;
    int n = i / K, k = i - n * K;
    float v;
    if (split) v = (n < 64) ? Wa[k * 64 + n] : Wb[k * 64 + (n - 64)];
    else       v = Wa[k * 128 + n];
    __nv_bfloat16 h = __float2bfloat16_rn(v);
    __nv_bfloat16 l = __float2bfloat16_rn(v - __bfloat162float(h));
    g_Bh16[i] = h;
    g_Bl16[i] = l;
}

// ---------------- bf16 split-3 tensor-core GEMM ----------------------------
// C[M x 128] = A[M x K] @ B[K x 128]; per-CTA 128x128 tile, 8 warps of 32x64.
// Smem rows padded to 80B -> conflict-free ldmatrix (8-row phase hits all 32 banks).
static constexpr int ROWB   = 80;                 // bytes per 32-elem bf16 row (padded)
static constexpr int AHALF  = 128 * ROWB;         // 10240: one [128][32] bf16 array
static constexpr int STAGE  = 4 * AHALF;          // Ah | Al | Bh | Bl = 40960
static constexpr int GEMM_SMEM = 2 * STAGE;       // 81920

template <int K, int SPLIT>
__global__ __launch_bounds__(256) void k_tgemm(
    const float* __restrict__ A,
    const float* __restrict__ bias1, const float* __restrict__ bias2,
    float* __restrict__ C1, float* __restrict__ C2)
{
    extern __shared__ __align__(256) char smem[];
    constexpr int NCH = K / 32;
    const int tid  = threadIdx.x;
    const int wid  = tid >> 5;
    const int lane = tid & 31;
    const int warp_m = wid & 3;      // rows warp_m*32
    const int warp_n = wid >> 2;     // cols warp_n*64
    const uint32_t sb = smem_u32(smem);
    const int rowBase = blockIdx.x * 128;

    // per-lane ldmatrix offsets (non-trans, x4)
    const uint32_t a_off = (uint32_t)(((lane & 7) + ((lane >> 3) & 1) * 8) * ROWB
                                      + ((lane >> 4) & 1) * 16);
    const uint32_t b_off = (uint32_t)((((lane >> 4) & 1) * 8 + (lane & 7)) * ROWB
                                      + ((lane >> 3) & 1) * 16);

    float acc[2][8][4];
#pragma unroll
    for (int t = 0; t < 2; t++)
#pragma unroll
        for (int j = 0; j < 8; j++)
#pragma unroll
            for (int v = 0; v < 4; v++) acc[t][j][v] = 0.f;

    // loader index assignments
    const int ar = tid >> 1;                 // A: 128 rows, 2 thr/row
    const int aq = (tid & 1) * 4;            // A: quad base; 4 iters -> quads 0..7
    const int br = tid >> 1;                 // B: 128 rows
    const int bq = (tid & 1) << 1;           // B: 16B chunk base; 2 iters -> 0..3

    auto sts_chunk = [&](int s, const float4* pa, const uint4* pbh, const uint4* pbl) {
        char* st = smem + s * STAGE;
#pragma unroll
        for (int it = 0; it < 4; it++) {
            int q = aq + it;                 // quad index 0..7 (cols q*4)
            float4 v = pa[it];
            __nv_bfloat162 h01 = __floats2bfloat162_rn(v.x, v.y);
            __nv_bfloat162 h23 = __floats2bfloat162_rn(v.z, v.w);
            float2 hf0 = __bfloat1622float2(h01);
            float2 hf1 = __bfloat1622float2(h23);
            __nv_bfloat162 l01 = __floats2bfloat162_rn(v.x - hf0.x, v.y - hf0.y);
            __nv_bfloat162 l23 = __floats2bfloat162_rn(v.z - hf1.x, v.w - hf1.y);
            uint32_t off = (uint32_t)(ar * ROWB + q * 8);
            *reinterpret_cast<__nv_bfloat162*>(st + off)         = h01;
            *reinterpret_cast<__nv_bfloat162*>(st + off + 4)     = h23;
            *reinterpret_cast<__nv_bfloat162*>(st + AHALF + off)     = l01;
            *reinterpret_cast<__nv_bfloat162*>(st + AHALF + off + 4) = l23;
        }
#pragma unroll
        for (int it = 0; it < 2; it++) {
            int q = bq + it;                 // 16B chunk 0..3
            uint32_t off = (uint32_t)(br * ROWB + q * 16);
            *reinterpret_cast<uint4*>(st + 2 * AHALF + off) = pbh[it];
            *reinterpret_cast<uint4*>(st + 3 * AHALF + off) = pbl[it];
        }
    };

    auto ldg_chunk = [&](int c, float4* pa, uint4* pbh, uint4* pbl) {
#pragma unroll
        for (int it = 0; it < 4; it++) {
            int q = aq + it;
            int row = rowBase + ar;
            float4 v = make_float4(0.f, 0.f, 0.f, 0.f);
            if (row < NN)
                v = *reinterpret_cast<const float4*>(&A[(size_t)row * K + c * 32 + q * 4]);
            pa[it] = v;
        }
#pragma unroll
        for (int it = 0; it < 2; it++) {
            int q = bq + it;
            size_t idx = (size_t)br * K + c * 32 + q * 8;    // bf16 elements
            pbh[it] = *reinterpret_cast<const uint4*>(&g_Bh16[idx]);
            pbl[it] = *reinterpret_cast<const uint4*>(&g_Bl16[idx]);
        }
    };

    {   // prologue: chunk 0 -> stage 0
        float4 pa[4]; uint4 pbh[2], pbl[2];
        ldg_chunk(0, pa, pbh, pbl);
        sts_chunk(0, pa, pbh, pbl);
    }
    __syncthreads();

    for (int c = 0; c < NCH; c++) {
        const int s = c & 1;
        float4 pa[4]; uint4 pbh[2], pbl[2];
        if (c + 1 < NCH) ldg_chunk(c + 1, pa, pbh, pbl);

        const uint32_t aBaseH = sb + s * STAGE + (uint32_t)(warp_m * 32) * ROWB;
        const uint32_t bBaseH = sb + s * STAGE + 2 * AHALF + (uint32_t)(warp_n * 64) * ROWB;

#pragma unroll
        for (int sk = 0; sk < 2; sk++) {
            uint32_t ah[2][4], al[2][4];
#pragma unroll
            for (int t = 0; t < 2; t++) {
                uint32_t ad = aBaseH + (uint32_t)(t * 16 * ROWB + sk * 32) + a_off;
                LDSM_X4(ah[t][0], ah[t][1], ah[t][2], ah[t][3], ad);
                LDSM_X4(al[t][0], al[t][1], al[t][2], al[t][3], ad + AHALF);
            }
            uint32_t bh[4][4], bl[4][4];
#pragma unroll
            for (int jp = 0; jp < 4; jp++) {
                uint32_t bd = bBaseH + (uint32_t)(jp * 16 * ROWB + sk * 32) + b_off;
                LDSM_X4(bh[jp][0], bh[jp][1], bh[jp][2], bh[jp][3], bd);
                LDSM_X4(bl[jp][0], bl[jp][1], bl[jp][2], bl[jp][3], bd + AHALF);
            }
#pragma unroll
            for (int t = 0; t < 2; t++)
#pragma unroll
                for (int j = 0; j < 8; j++) {
                    int jp = j >> 1, o = (j & 1) * 2;
                    MMA_BF16(acc[t][j], ah[t], bh[jp][o], bh[jp][o + 1]);
                    MMA_BF16(acc[t][j], ah[t], bl[jp][o], bl[jp][o + 1]);
                    MMA_BF16(acc[t][j], al[t], bh[jp][o], bh[jp][o + 1]);
                }
        }

        if (c + 1 < NCH) sts_chunk(s ^ 1, pa, pbh, pbl);
        __syncthreads();
    }

    // ---------------- epilogue ----------------
    const int r0 = rowBase + warp_m * 32 + (lane >> 2);
    const int cb = (lane & 3) * 2;
#pragma unroll
    for (int t = 0; t < 2; t++) {
#pragma unroll
        for (int j = 0; j < 8; j++) {
            int col = warp_n * 64 + j * 8 + cb;   // global col 0..127
            float2 v0 = make_float2(acc[t][j][0], acc[t][j][1]);
            float2 v1 = make_float2(acc[t][j][2], acc[t][j][3]);
            int ra = r0 + t * 16;
            int rb = ra + 8;
            if (SPLIT) {
                const float* bias = warp_n ? bias2 : bias1;
                float*       C    = warp_n ? C2    : C1;
                int lc = col - warp_n * 64;       // 0..63
                float bx = bias[lc], by = bias[lc + 1];
                v0.x += bx; v0.y += by;
                v1.x += bx; v1.y += by;
                if (ra < NN) *reinterpret_cast<float2*>(&C[(size_t)ra * 64 + lc]) = v0;
                if (rb < NN) *reinterpret_cast<float2*>(&C[(size_t)rb * 64 + lc]) = v1;
            } else {
                if (ra < NN) *reinterpret_cast<float2*>(&C1[(size_t)ra * 128 + col]) = v0;
                if (rb < NN) *reinterpret_cast<float2*>(&C1[(size_t)rb * 128 + col]) = v1;
            }
        }
    }
}

// ---------------- aggregation ----------------------------------------------
template <int MODE>
__global__ __launch_bounds__(256) void k_agg(
    const float4* __restrict__ G4, const float* __restrict__ bias,
    float4* __restrict__ O4)
{
    int warp = (blockIdx.x * blockDim.x + threadIdx.x) >> 5;
    int lane = threadIdx.x & 31;
    if (warp >= NN) return;
    int e0 = g_off[warp], e1 = g_off[warp + 1];
    float dii = g_dis[warp];
    float w0 = dii * dii;
    float4 gs = G4[(long)warp * 32 + lane];
    float4 acc;
    acc.x = w0 * gs.x; acc.y = w0 * gs.y; acc.z = w0 * gs.z; acc.w = w0 * gs.w;
#pragma unroll 4
    for (int e = e0; e < e1; e++) {
        int   s = g_csr_src[e];
        float w = g_csr_norm[e];
        float4 m = G4[(long)s * 32 + lane];
        acc.x = fmaf(w, m.x, acc.x);
        acc.y = fmaf(w, m.y, acc.y);
        acc.z = fmaf(w, m.z, acc.z);
        acc.w = fmaf(w, m.w, acc.w);
    }
    if (MODE == 1) {
        float4 b = reinterpret_cast<const float4*>(bias)[lane];
        acc.x = fmaxf(acc.x + b.x, 0.f);
        acc.y = fmaxf(acc.y + b.y, 0.f);
        acc.z = fmaxf(acc.z + b.z, 0.f);
        acc.w = fmaxf(acc.w + b.w, 0.f);
    }
    O4[(long)warp * 32 + lane] = acc;
}

// ---------------- launch ----------------------------------------------------
extern "C" void kernel_launch(void* const* d_in, const int* in_sizes, int n_in,
                              void* d_out, int out_size) {
    const float* x  = (const float*)d_in[0];
    const void*  ei = d_in[1];
    const float* W1 = (const float*)d_in[2];
    const float* b1 = (const float*)d_in[3];
    const float* W2 = (const float*)d_in[4];
    const float* b2 = (const float*)d_in[5];
    const float* Wm = (const float*)d_in[6];
    const float* bm = (const float*)d_in[7];
    const float* Ws = (const float*)d_in[8];
    const float* bs = (const float*)d_in[9];
    float* outM = (float*)d_out;
    float* outS = outM + (long)NN * ZD;

    float *pA = nullptr, *pB = nullptr;
    cudaGetSymbolAddress((void**)&pA, g_bufA);
    cudaGetSymbolAddress((void**)&pB, g_bufB);

    cudaFuncSetAttribute(k_tgemm<512, 0>, cudaFuncAttributeMaxDynamicSharedMemorySize, GEMM_SMEM);
    cudaFuncSetAttribute(k_tgemm<128, 0>, cudaFuncAttributeMaxDynamicSharedMemorySize, GEMM_SMEM);
    cudaFuncSetAttribute(k_tgemm<128, 1>, cudaFuncAttributeMaxDynamicSharedMemorySize, GEMM_SMEM);

    const int T = 256;
    const int nblk_scan = (NN + 1023) / 1024;

    k_detect<<<1, 32>>>((const int*)ei);
    k_zero_cnt<<<(NN + T - 1) / T, T>>>();
    k_count<<<(EE + T - 1) / T, T>>>(ei);
    k_degdis<<<(NN + T - 1) / T, T>>>();
    k_scan1<<<nblk_scan, 1024>>>();
    k_scan2<<<1, 64>>>(nblk_scan);
    k_scan3<<<(NN + T - 1) / T, T>>>();
    k_fill<<<(EE + T - 1) / T, T>>>(ei);

    const int gb = (NN + 127) / 128;             // 391 CTAs
    const int ab = (NN * 32 + T - 1) / T;        // agg blocks

    // layer 1: G = x @ W1 ; h1 = relu(A G + b1)
    k_prepB<<<(128 * 512 + T - 1) / T, T>>>(W1, nullptr, 512, 0);
    k_tgemm<512, 0><<<gb, 256, GEMM_SMEM>>>(x, nullptr, nullptr, pA, nullptr);
    k_agg<1><<<ab, T>>>((const float4*)pA, b1, (float4*)pB);
    // layer 2: G = h1 @ W2 ; h2 = relu(A G + b2)
    k_prepB<<<(128 * 128 + T - 1) / T, T>>>(W2, nullptr, 128, 0);
    k_tgemm<128, 0><<<gb, 256, GEMM_SMEM>>>(pB, nullptr, nullptr, pA, nullptr);
    k_agg<1><<<ab, T>>>((const float4*)pA, b2, (float4*)pB);
    // heads: AG = A h2 ; [z_mean | z_log_std] = AG [Wm | Ws] + [bm | bs]
    k_agg<0><<<ab, T>>>((const float4*)pB, nullptr, (float4*)pA);
    k_prepB<<<(128 * 128 + T - 1) / T, T>>>(Wm, Ws, 128, 1);
    k_tgemm<128, 1><<<gb, 256, GEMM_SMEM>>>(pA, bm, bs, outM, outS);
}

// round 6
// speedup vs baseline: 1.6064x; 1.0499x over previous
#include <cuda_runtime.h>
#include <cuda_bf16.h>
#include <cuda_fp16.h>
#include <cstdint>

#define NN 50000
#define EE 800000
#define FD 128
#define ZD 64

// ---------------- scratch (device globals; no allocation allowed) ----------
__device__ __align__(256) float  g_bufA[NN * FD];
__device__ __align__(256) __half g_H16[NN * FD];
__device__ __align__(256) __nv_bfloat16 g_Bh16[128 * 512];
__device__ __align__(256) __nv_bfloat16 g_Bl16[128 * 512];
__device__ int   g_cnt[NN];
__device__ int   g_cursor[NN];
__device__ int   g_off[NN + 1];
__device__ int   g_bsum[64];
__device__ int   g_boff[64];
__device__ float g_dis[NN];
__device__ int   g_csr_src[EE];
__device__ float g_csr_norm[EE];
__device__ int   g_is64;

// ---------------- PTX helpers ----------------------------------------------
__device__ __forceinline__ uint32_t smem_u32(const void* p) {
    uint32_t a;
    asm("{ .reg .u64 t; cvta.to.shared.u64 t, %1; cvt.u32.u64 %0, t; }"
        : "=r"(a) : "l"(p));
    return a;
}

#define LDSM_X4(r0, r1, r2, r3, addr) \
    asm volatile("ldmatrix.sync.aligned.m8n8.x4.shared.b16 {%0,%1,%2,%3}, [%4];" \
        : "=r"(r0), "=r"(r1), "=r"(r2), "=r"(r3) : "r"(addr))

#define MMA_BF16(d, a, b0, b1) \
    asm volatile("mma.sync.aligned.m16n8k16.row.col.f32.bf16.bf16.f32 " \
        "{%0,%1,%2,%3}, {%4,%5,%6,%7}, {%8,%9}, {%0,%1,%2,%3};" \
        : "+f"((d)[0]), "+f"((d)[1]), "+f"((d)[2]), "+f"((d)[3]) \
        : "r"((a)[0]), "r"((a)[1]), "r"((a)[2]), "r"((a)[3]), "r"(b0), "r"(b1))

// ---------------- preprocessing --------------------------------------------
__device__ __forceinline__ int edge_at(const void* eiv, long idx) {
    if (g_is64) return (int)((const long long*)eiv)[idx];
    return ((const int*)eiv)[idx];
}

// zero counts + detect edge dtype (block 0, warp 0)
__global__ void k_init(const int* __restrict__ ei32) {
    int i = blockIdx.x * blockDim.x + threadIdx.x;
    if (i < NN) g_cnt[i] = 0;
    if (blockIdx.x == 0 && threadIdx.x < 32) {
        int v = ei32[2 * threadIdx.x + 1];
        unsigned m = __ballot_sync(0xffffffffu, v != 0);
        if (threadIdx.x == 0) g_is64 = (m == 0) ? 1 : 0;
    }
}

__global__ void k_count(const void* __restrict__ eiv) {
    int e = blockIdx.x * blockDim.x + threadIdx.x;
    if (e < EE) {
        int d = edge_at(eiv, (long)EE + e);
        atomicAdd(&g_cnt[d], 1);
    }
}

// exclusive scan of g_cnt into g_off; also writes g_dis = rsqrt(deg+1)
__global__ void k_scan1() {
    __shared__ int ws[32];
    int i = blockIdx.x * 1024 + threadIdx.x;
    int lane = threadIdx.x & 31, wid = threadIdx.x >> 5;
    int v = (i < NN) ? g_cnt[i] : 0;
    int orig = v;
    if (i < NN) g_dis[i] = rsqrtf((float)(orig + 1));
#pragma unroll
    for (int d = 1; d < 32; d <<= 1) {
        int n = __shfl_up_sync(0xffffffffu, v, d);
        if (lane >= d) v += n;
    }
    if (lane == 31) ws[wid] = v;
    __syncthreads();
    if (wid == 0) {
        int s = ws[lane];
#pragma unroll
        for (int d = 1; d < 32; d <<= 1) {
            int n = __shfl_up_sync(0xffffffffu, s, d);
            if (lane >= d) s += n;
        }
        ws[lane] = s;
    }
    __syncthreads();
    int incl = v + (wid > 0 ? ws[wid - 1] : 0);
    if (i < NN) g_off[i] = incl - orig;
    if (threadIdx.x == 1023) g_bsum[blockIdx.x] = incl;
}

__global__ void k_scan2(int nblk) {
    __shared__ int w0sum;
    int t = threadIdx.x, lane = t & 31, wid = t >> 5;
    int v = (t < nblk) ? g_bsum[t] : 0;
    int orig = v;
#pragma unroll
    for (int d = 1; d < 32; d <<= 1) {
        int n = __shfl_up_sync(0xffffffffu, v, d);
        if (lane >= d) v += n;
    }
    if (wid == 0 && lane == 31) w0sum = v;
    __syncthreads();
    int incl = v + (wid == 1 ? w0sum : 0);
    if (t < nblk) g_boff[t] = incl - orig;
}

__global__ void k_scan3() {
    int i = blockIdx.x * blockDim.x + threadIdx.x;
    if (i < NN) {
        g_off[i] += g_boff[i >> 10];
        g_cursor[i] = 0;
    }
    if (i == 0) g_off[NN] = EE;
}

__global__ void k_fill(const void* __restrict__ eiv) {
    int e = blockIdx.x * blockDim.x + threadIdx.x;
    if (e < EE) {
        int s = edge_at(eiv, e);
        int d = edge_at(eiv, (long)EE + e);
        int pos = g_off[d] + atomicAdd(&g_cursor[d], 1);
        g_csr_src[pos]  = s;
        g_csr_norm[pos] = g_dis[s] * g_dis[d];
    }
}

// ---------------- W prep: split to bf16 hi/lo, transpose to [N=128][K] -----
__global__ void k_prepB(const float* __restrict__ Wa, const float* __restrict__ Wb,
                        int K, int split) {
    int i = blockIdx.x * blockDim.x + threadIdx.x;
    if (i >= 128 * K) return;
    int n = i / K, k = i - n * K;
    float v;
    if (split) v = (n < 64) ? Wa[k * 64 + n] : Wb[k * 64 + (n - 64)];
    else       v = Wa[k * 128 + n];
    __nv_bfloat16 h = __float2bfloat16_rn(v);
    __nv_bfloat16 l = __float2bfloat16_rn(v - __bfloat162float(h));
    g_Bh16[i] = h;
    g_Bl16[i] = l;
}

// ---------------- bf16 split-3 tensor-core GEMM, fp16 output ---------------
// C_fp16[M x 128] = A[M x K] @ B[K x 128]; 128x128 CTA tile, 8 warps of 32x64.
static constexpr int ROWB   = 80;                 // padded bf16 row (conflict-free ldmatrix)
static constexpr int AHALF  = 128 * ROWB;         // 10240
static constexpr int STAGE  = 4 * AHALF;          // Ah | Al | Bh | Bl
static constexpr int GEMM_SMEM = 2 * STAGE;       // 81920

template <int K>
__global__ __launch_bounds__(256) void k_tgemm(
    const float* __restrict__ A, __half* __restrict__ C)
{
    extern __shared__ __align__(256) char smem[];
    constexpr int NCH = K / 32;
    const int tid  = threadIdx.x;
    const int wid  = tid >> 5;
    const int lane = tid & 31;
    const int warp_m = wid & 3;
    const int warp_n = wid >> 2;
    const uint32_t sb = smem_u32(smem);
    const int rowBase = blockIdx.x * 128;

    const uint32_t a_off = (uint32_t)(((lane & 7) + ((lane >> 3) & 1) * 8) * ROWB
                                      + ((lane >> 4) & 1) * 16);
    const uint32_t b_off = (uint32_t)((((lane >> 4) & 1) * 8 + (lane & 7)) * ROWB
                                      + ((lane >> 3) & 1) * 16);

    float acc[2][8][4];
#pragma unroll
    for (int t = 0; t < 2; t++)
#pragma unroll
        for (int j = 0; j < 8; j++)
#pragma unroll
            for (int v = 0; v < 4; v++) acc[t][j][v] = 0.f;

    const int ar = tid >> 1;
    const int aq = (tid & 1) * 4;
    const int br = tid >> 1;
    const int bq = (tid & 1) << 1;

    auto sts_chunk = [&](int s, const float4* pa, const uint4* pbh, const uint4* pbl) {
        char* st = smem + s * STAGE;
#pragma unroll
        for (int it = 0; it < 4; it++) {
            int q = aq + it;
            float4 v = pa[it];
            __nv_bfloat162 h01 = __floats2bfloat162_rn(v.x, v.y);
            __nv_bfloat162 h23 = __floats2bfloat162_rn(v.z, v.w);
            float2 hf0 = __bfloat1622float2(h01);
            float2 hf1 = __bfloat1622float2(h23);
            __nv_bfloat162 l01 = __floats2bfloat162_rn(v.x - hf0.x, v.y - hf0.y);
            __nv_bfloat162 l23 = __floats2bfloat162_rn(v.z - hf1.x, v.w - hf1.y);
            uint32_t off = (uint32_t)(ar * ROWB + q * 8);
            *reinterpret_cast<__nv_bfloat162*>(st + off)             = h01;
            *reinterpret_cast<__nv_bfloat162*>(st + off + 4)         = h23;
            *reinterpret_cast<__nv_bfloat162*>(st + AHALF + off)     = l01;
            *reinterpret_cast<__nv_bfloat162*>(st + AHALF + off + 4) = l23;
        }
#pragma unroll
        for (int it = 0; it < 2; it++) {
            int q = bq + it;
            uint32_t off = (uint32_t)(br * ROWB + q * 16);
            *reinterpret_cast<uint4*>(st + 2 * AHALF + off) = pbh[it];
            *reinterpret_cast<uint4*>(st + 3 * AHALF + off) = pbl[it];
        }
    };

    auto ldg_chunk = [&](int c, float4* pa, uint4* pbh, uint4* pbl) {
#pragma unroll
        for (int it = 0; it < 4; it++) {
            int q = aq + it;
            int row = rowBase + ar;
            float4 v = make_float4(0.f, 0.f, 0.f, 0.f);
            if (row < NN)
                v = *reinterpret_cast<const float4*>(&A[(size_t)row * K + c * 32 + q * 4]);
            pa[it] = v;
        }
#pragma unroll
        for (int it = 0; it < 2; it++) {
            int q = bq + it;
            size_t idx = (size_t)br * K + c * 32 + q * 8;
            pbh[it] = *reinterpret_cast<const uint4*>(&g_Bh16[idx]);
            pbl[it] = *reinterpret_cast<const uint4*>(&g_Bl16[idx]);
        }
    };

    {
        float4 pa[4]; uint4 pbh[2], pbl[2];
        ldg_chunk(0, pa, pbh, pbl);
        sts_chunk(0, pa, pbh, pbl);
    }
    __syncthreads();

    for (int c = 0; c < NCH; c++) {
        const int s = c & 1;
        float4 pa[4]; uint4 pbh[2], pbl[2];
        if (c + 1 < NCH) ldg_chunk(c + 1, pa, pbh, pbl);

        const uint32_t aBaseH = sb + s * STAGE + (uint32_t)(warp_m * 32) * ROWB;
        const uint32_t bBaseH = sb + s * STAGE + 2 * AHALF + (uint32_t)(warp_n * 64) * ROWB;

#pragma unroll
        for (int sk = 0; sk < 2; sk++) {
            uint32_t ah[2][4], al[2][4];
#pragma unroll
            for (int t = 0; t < 2; t++) {
                uint32_t ad = aBaseH + (uint32_t)(t * 16 * ROWB + sk * 32) + a_off;
                LDSM_X4(ah[t][0], ah[t][1], ah[t][2], ah[t][3], ad);
                LDSM_X4(al[t][0], al[t][1], al[t][2], al[t][3], ad + AHALF);
            }
            uint32_t bh[4][4], bl[4][4];
#pragma unroll
            for (int jp = 0; jp < 4; jp++) {
                uint32_t bd = bBaseH + (uint32_t)(jp * 16 * ROWB + sk * 32) + b_off;
                LDSM_X4(bh[jp][0], bh[jp][1], bh[jp][2], bh[jp][3], bd);
                LDSM_X4(bl[jp][0], bl[jp][1], bl[jp][2], bl[jp][3], bd + AHALF);
            }
#pragma unroll
            for (int t = 0; t < 2; t++)
#pragma unroll
                for (int j = 0; j < 8; j++) {
                    int jp = j >> 1, o = (j & 1) * 2;
                    MMA_BF16(acc[t][j], ah[t], bh[jp][o], bh[jp][o + 1]);
                    MMA_BF16(acc[t][j], ah[t], bl[jp][o], bl[jp][o + 1]);
                    MMA_BF16(acc[t][j], al[t], bh[jp][o], bh[jp][o + 1]);
                }
        }

        if (c + 1 < NCH) sts_chunk(s ^ 1, pa, pbh, pbl);
        __syncthreads();
    }

    // epilogue: fp16 stores
    const int r0 = rowBase + warp_m * 32 + (lane >> 2);
    const int cb = (lane & 3) * 2;
#pragma unroll
    for (int t = 0; t < 2; t++) {
#pragma unroll
        for (int j = 0; j < 8; j++) {
            int col = warp_n * 64 + j * 8 + cb;
            int ra = r0 + t * 16;
            int rb = ra + 8;
            if (ra < NN)
                *reinterpret_cast<__half2*>(&C[(size_t)ra * 128 + col]) =
                    __floats2half2_rn(acc[t][j][0], acc[t][j][1]);
            if (rb < NN)
                *reinterpret_cast<__half2*>(&C[(size_t)rb * 128 + col]) =
                    __floats2half2_rn(acc[t][j][2], acc[t][j][3]);
        }
    }
}

// ---------------- aggregation (fp16 gathers, fp32 accumulate) --------------
// MODE 1: O = relu(sum + biasA), fp32 [node][128]
// MODE 2: cols 0-63 -> OA + biasA, cols 64-127 -> OB + biasB (fp32 [node][64])
template <int MODE>
__global__ __launch_bounds__(256) void k_agg(
    const uint2* __restrict__ G,   // fp16 table: [node][32] x 8B
    const float* __restrict__ biasA, const float* __restrict__ biasB,
    float* __restrict__ OA, float* __restrict__ OB)
{
    int node = (blockIdx.x * blockDim.x + threadIdx.x) >> 5;
    int lane = threadIdx.x & 31;
    if (node >= NN) return;
    int e0 = g_off[node], e1 = g_off[node + 1];
    float dii = g_dis[node];
    float w0 = dii * dii;
    uint2 r = G[(size_t)node * 32 + lane];
    float2 p0 = __half22float2(*reinterpret_cast<__half2*>(&r.x));
    float2 p1 = __half22float2(*reinterpret_cast<__half2*>(&r.y));
    float4 acc = make_float4(w0 * p0.x, w0 * p0.y, w0 * p1.x, w0 * p1.y);
#pragma unroll 4
    for (int e = e0; e < e1; e++) {
        int   s = g_csr_src[e];        // warp-broadcast
        float w = g_csr_norm[e];
        uint2 m = G[(size_t)s * 32 + lane];
        float2 q0 = __half22float2(*reinterpret_cast<__half2*>(&m.x));
        float2 q1 = __half22float2(*reinterpret_cast<__half2*>(&m.y));
        acc.x = fmaf(w, q0.x, acc.x);
        acc.y = fmaf(w, q0.y, acc.y);
        acc.z = fmaf(w, q1.x, acc.z);
        acc.w = fmaf(w, q1.y, acc.w);
    }
    if (MODE == 1) {
        float4 b = reinterpret_cast<const float4*>(biasA)[lane];
        acc.x = fmaxf(acc.x + b.x, 0.f);
        acc.y = fmaxf(acc.y + b.y, 0.f);
        acc.z = fmaxf(acc.z + b.z, 0.f);
        acc.w = fmaxf(acc.w + b.w, 0.f);
        reinterpret_cast<float4*>(OA)[(size_t)node * 32 + lane] = acc;
    } else {
        if (lane < 16) {
            float4 b = reinterpret_cast<const float4*>(biasA)[lane];
            acc.x += b.x; acc.y += b.y; acc.z += b.z; acc.w += b.w;
            reinterpret_cast<float4*>(OA)[(size_t)node * 16 + lane] = acc;
        } else {
            float4 b = reinterpret_cast<const float4*>(biasB)[lane - 16];
            acc.x += b.x; acc.y += b.y; acc.z += b.z; acc.w += b.w;
            reinterpret_cast<float4*>(OB)[(size_t)node * 16 + (lane - 16)] = acc;
        }
    }
}

// ---------------- launch ----------------------------------------------------
extern "C" void kernel_launch(void* const* d_in, const int* in_sizes, int n_in,
                              void* d_out, int out_size) {
    const float* x  = (const float*)d_in[0];
    const void*  ei = d_in[1];
    const float* W1 = (const float*)d_in[2];
    const float* b1 = (const float*)d_in[3];
    const float* W2 = (const float*)d_in[4];
    const float* b2 = (const float*)d_in[5];
    const float* Wm = (const float*)d_in[6];
    const float* bm = (const float*)d_in[7];
    const float* Ws = (const float*)d_in[8];
    const float* bs = (const float*)d_in[9];
    float* outM = (float*)d_out;
    float* outS = outM + (long)NN * ZD;

    float*  pA = nullptr;
    __half* pH = nullptr;
    cudaGetSymbolAddress((void**)&pA, g_bufA);
    cudaGetSymbolAddress((void**)&pH, g_H16);

    cudaFuncSetAttribute(k_tgemm<512>, cudaFuncAttributeMaxDynamicSharedMemorySize, GEMM_SMEM);
    cudaFuncSetAttribute(k_tgemm<128>, cudaFuncAttributeMaxDynamicSharedMemorySize, GEMM_SMEM);

    const int T = 256;
    const int nblk_scan = (NN + 1023) / 1024;

    // preprocessing: CSR by dst + sym-norm weights
    k_init<<<(NN + T - 1) / T, T>>>((const int*)ei);
    k_count<<<(EE + T - 1) / T, T>>>(ei);
    k_scan1<<<nblk_scan, 1024>>>();
    k_scan2<<<1, 64>>>(nblk_scan);
    k_scan3<<<(NN + T - 1) / T, T>>>();
    k_fill<<<(EE + T - 1) / T, T>>>(ei);

    const int gb = (NN + 127) / 128;           // 391 CTAs
    const int ab = (NN * 32 + T - 1) / T;      // agg blocks

    // layer 1: H16 = fp16(x @ W1) ; h1 = relu(A H16 + b1)
    k_prepB<<<(128 * 512 + T - 1) / T, T>>>(W1, nullptr, 512, 0);
    k_tgemm<512><<<gb, 256, GEMM_SMEM>>>(x, pH);
    k_agg<1><<<ab, T>>>((const uint2*)pH, b1, nullptr, pA, nullptr);
    // layer 2: H16 = fp16(h1 @ W2) ; h2 = relu(A H16 + b2)
    k_prepB<<<(128 * 128 + T - 1) / T, T>>>(W2, nullptr, 128, 0);
    k_tgemm<128><<<gb, 256, GEMM_SMEM>>>(pA, pH);
    k_agg<1><<<ab, T>>>((const uint2*)pH, b2, nullptr, pA, nullptr);
    // heads: H16 = fp16(h2 @ [Wm|Ws]) ; [z_mean|z_log_std] = A H16 + [bm|bs]
    k_prepB<<<(128 * 128 + T - 1) / T, T>>>(Wm, Ws, 128, 1);
    k_tgemm<128><<<gb, 256, GEMM_SMEM>>>(pA, pH);
    k_agg<2><<<ab, T>>>((const uint2*)pH, bm, bs, outM, outS);
}